// round 11
// baseline (speedup 1.0000x reference)
#include <cuda_runtime.h>
#include <cstdint>

// Problem shape (fixed by the dataset)
#define BB   2
#define NN   20000
#define KK   16
#define CIN  128
#define MM   9
#define COUT 128
#define MP   16
#define NROWS (BB*NN)           // 40000
#define KDIM  (MM*CIN)          // 1152

// Scratch (device globals: allocation-free per harness rules)
__device__ float g_xu[(size_t)NROWS * MP];        // 2.56 MB
__device__ float g_Y [(size_t)NROWS * KDIM];      // 184 MB  (tf32-rounded fp32)
__device__ float g_WT[KDIM * COUT];               // 589 KB  WT[m*128+c][o], tf32-rounded

// ---- packed f32x2 helpers -------------------------------------------------
__device__ __forceinline__ unsigned long long pk2(float lo, float hi){
    unsigned long long r;
    asm("mov.b64 %0, {%1, %2};" : "=l"(r) : "f"(lo), "f"(hi));
    return r;
}
__device__ __forceinline__ void fma2(unsigned long long& d,
                                     unsigned long long a, unsigned long long b){
    asm("fma.rn.f32x2 %0, %1, %2, %0;" : "+l"(d) : "l"(a), "l"(b));
}
__device__ __forceinline__ float2 up2(unsigned long long v){
    float lo, hi;
    asm("mov.b64 {%0, %1}, %2;" : "=f"(lo), "=f"(hi) : "l"(v));
    return make_float2(lo, hi);
}
__device__ __forceinline__ float tf32r(float v){     // round-to-nearest tf32
    uint32_t r; asm("cvt.rna.tf32.f32 %0, %1;" : "=r"(r) : "f"(v));
    return __uint_as_float(r);
}
__device__ __forceinline__ uint32_t smem_u32(const void* p){
    uint32_t a;
    asm("{ .reg .u64 t; cvta.to.shared.u64 t, %1; cvt.u32.u64 %0, t; }" : "=r"(a) : "l"(p));
    return a;
}
__device__ __forceinline__ void cpasync16(uint32_t dst, const void* src, bool pred){
    int sz = pred ? 16 : 0;
    asm volatile("cp.async.cg.shared.global [%0], [%1], 16, %2;"
                 :: "r"(dst), "l"(src), "r"(sz) : "memory");
}

// ---- Kernel A: xu[b,n,m] = dot(x[b,n,:], u[m,:]) -------------------------
__global__ void xu_kernel(const float* __restrict__ x, const float* __restrict__ u){
    __shared__ float su[MM*CIN];
    for (int i = threadIdx.x; i < MM*CIN; i += blockDim.x) su[i] = u[i];
    __syncthreads();
    int gw  = (blockIdx.x * blockDim.x + threadIdx.x) >> 5;
    int lid = threadIdx.x & 31;
    if (gw >= NROWS) return;
    float4 xv = *(const float4*)(x + (size_t)gw*CIN + lid*4);
    float p[MM];
    #pragma unroll
    for (int m = 0; m < MM; ++m){
        float4 uv = *(const float4*)(su + m*CIN + lid*4);
        p[m] = xv.x*uv.x + xv.y*uv.y + xv.z*uv.z + xv.w*uv.w;
    }
    #pragma unroll
    for (int off = 16; off; off >>= 1)
        #pragma unroll
        for (int m = 0; m < MM; ++m)
            p[m] += __shfl_xor_sync(0xffffffffu, p[m], off);
    if (lid == 0){
        float* dst = g_xu + (size_t)gw*MP;
        #pragma unroll
        for (int m = 0; m < MM; ++m) dst[m] = p[m];
    }
}

// ---- Kernel B: W[m][o][c] -> WT[m*128+c][o], tf32-rounded ----------------
__global__ void wt_kernel(const float* __restrict__ W){
    int idx = blockIdx.x*blockDim.x + threadIdx.x;
    if (idx >= MM*COUT*CIN) return;
    int c = idx % CIN;
    int o = (idx / CIN) % COUT;
    int m = idx / (CIN*COUT);
    g_WT[(m*CIN + c)*COUT + o] = tf32r(W[idx]);
}

// ---- Fused kernel: phase 1 = qy (softmax+deg_inv fold, Y block to global,
// L2-hot), phase 2 = tf32 mma.sync GEMM over the same 128 rows.
// GEMM: BM=128, BN=128, BK=16, 256 threads (8 warps, 64x32 warp tiles),
// 3-stage cp.async pipeline, tail-safe drain.
#define BMg 128
#define BKg 16
#define ASTR 20            // 128*20 floats per A stage
#define BSTR 136           // 16*136 floats per B stage
#define AST_F (BMg*ASTR)   // 2560
#define BST_F (BKg*BSTR)   // 2176
#define BOFF_F (3*AST_F)   // B region starts after 3 A stages
#define GSMEM_BYTES ((3*AST_F + 3*BST_F)*4)   // 56832
#define NTg (KDIM/BKg)     // 72

__global__ void __launch_bounds__(256, 2)
fused_kernel(const float* __restrict__ x, const int* __restrict__ adj,
             const float* __restrict__ cb,
             const float* __restrict__ bias, float* __restrict__ out){
    extern __shared__ float sm[];
    int tid  = threadIdx.x;
    int lane = tid & 31, wid = tid >> 5;
    int row0 = blockIdx.x * BMg;

    // ================= Phase 1: qy for rows [row0, row0+128) =============
    {
        // qs aliases the (not yet used) pipeline smem: [8 warps][16][9]
        float* qs = sm;
        for (int it = 0; it < 16; ++it){
            int node = row0 + it*8 + wid;
            if (node < NROWS){
                int b = node / NN;
                int n = node - b*NN;

                int j = 0;
                if (lane < KK) j = adj[n*KK + lane];
                unsigned nz = __ballot_sync(0xffffffffu, j != 0);
                int   deg  = __popc(nz);
                float dinv = (deg > 0) ? (1.0f / (float)deg) : 0.0f;
                float* qw = qs + wid*(KK*MM);

                if (lane < KK){
                    if (j != 0){
                        const float* xs = g_xu + (size_t)node * MP;
                        const float* xp = g_xu + (size_t)(b*NN + (j-1)) * MP;
                        float lg[MM]; float mx = -1e30f;
                        #pragma unroll
                        for (int m = 0; m < MM; ++m){
                            lg[m] = xs[m] - xp[m] + cb[m];
                            mx = fmaxf(mx, lg[m]);
                        }
                        float s = 0.f;
                        #pragma unroll
                        for (int m = 0; m < MM; ++m){ lg[m] = __expf(lg[m] - mx); s += lg[m]; }
                        float r = dinv / s;
                        #pragma unroll
                        for (int m = 0; m < MM; ++m) qw[lane*MM + m] = lg[m] * r;
                    } else {
                        #pragma unroll
                        for (int m = 0; m < MM; ++m) qw[lane*MM + m] = 0.f;
                    }
                }
                __syncwarp();

                unsigned long long acc[MM][2];
                #pragma unroll
                for (int m = 0; m < MM; ++m){ acc[m][0] = 0ull; acc[m][1] = 0ull; }

                #pragma unroll
                for (int k = 0; k < KK; ++k){
                    int jk = __shfl_sync(0xffffffffu, j, k);
                    if (jk == 0) continue;
                    float4 p = *(const float4*)(x + (size_t)(b*NN + (jk-1))*CIN + lane*4);
                    unsigned long long p0 = pk2(p.x, p.y), p1 = pk2(p.z, p.w);
                    #pragma unroll
                    for (int m = 0; m < MM; ++m){
                        float qv = qw[k*MM + m];
                        unsigned long long q2 = pk2(qv, qv);
                        fma2(acc[m][0], q2, p0);
                        fma2(acc[m][1], q2, p1);
                    }
                }
                #pragma unroll
                for (int m = 0; m < MM; ++m){
                    float2 a  = up2(acc[m][0]);
                    float2 c2 = up2(acc[m][1]);
                    *(float4*)(g_Y + (size_t)node*KDIM + m*CIN + lane*4) =
                        make_float4(tf32r(a.x), tf32r(a.y), tf32r(c2.x), tf32r(c2.y));
                }
            }
        }
        __threadfence_block();   // order our global Y writes before phase-2 reads
        __syncthreads();
    }

    // ================= Phase 2: tf32 GEMM over rows [row0, row0+128) =====
    int warpM = wid >> 2, warpN = wid & 3;       // 2 x 4 warp grid, tile 64x32
    int g = lane >> 2, tig = lane & 3;

    uint32_t smb = smem_u32(sm);
    bool isA = tid < 128;
    bool arow_ok = isA && (row0 + tid) < NROWS;
    const float* Abase = g_Y + (size_t)(arow_ok ? (row0 + tid) : 0) * KDIM;
    int t2  = tid - 128;
    int bkr = t2 >> 3;                    // 0..15
    int bcb = (t2 & 7) * 16;              // 0..112

    float acc[4][4][4];
    #pragma unroll
    for (int mt = 0; mt < 4; ++mt)
        #pragma unroll
        for (int nt = 0; nt < 4; ++nt)
            #pragma unroll
            for (int i = 0; i < 4; ++i) acc[mt][nt][i] = 0.f;

    auto load_stage = [&](int t, int s){
        int kc = t * BKg;
        if (isA){
            uint32_t d = smb + (s*AST_F + tid*ASTR)*4;
            #pragma unroll
            for (int c = 0; c < 4; ++c)
                cpasync16(d + c*16, Abase + kc + c*4, arow_ok);
        } else {
            uint32_t d = smb + (BOFF_F + s*BST_F + bkr*BSTR + bcb)*4;
            const float* bsrc = g_WT + (size_t)(kc + bkr)*COUT + bcb;
            #pragma unroll
            for (int c = 0; c < 4; ++c)
                cpasync16(d + c*16, bsrc + c*4, true);
        }
        asm volatile("cp.async.commit_group;" ::: "memory");
    };

    load_stage(0, 0);
    load_stage(1, 1);

    for (int t = 0; t < NTg; ++t){
        int s = t % 3;
        // Committed-not-drained groups here: {t} plus {t+1} if it exists.
        if (t + 1 < NTg)
            asm volatile("cp.async.wait_group 1;" ::: "memory");
        else
            asm volatile("cp.async.wait_group 0;" ::: "memory");
        __syncthreads();
        if (t + 2 < NTg) load_stage(t + 2, (t + 2) % 3);

        const float* As_s = sm + s*AST_F;
        const float* Bs_s = sm + BOFF_F + s*BST_F;
        #pragma unroll
        for (int ks = 0; ks < BKg; ks += 8){
            uint32_t af[4][4], bf[4][2];
            #pragma unroll
            for (int mt = 0; mt < 4; ++mt){
                int r = warpM*64 + mt*16 + g;
                af[mt][0] = __float_as_uint(As_s[r*ASTR     + ks + tig    ]);
                af[mt][1] = __float_as_uint(As_s[(r+8)*ASTR + ks + tig    ]);
                af[mt][2] = __float_as_uint(As_s[r*ASTR     + ks + tig + 4]);
                af[mt][3] = __float_as_uint(As_s[(r+8)*ASTR + ks + tig + 4]);
            }
            #pragma unroll
            for (int nt = 0; nt < 4; ++nt){
                int c = warpN*32 + nt*8 + g;
                bf[nt][0] = __float_as_uint(Bs_s[(ks + tig    )*BSTR + c]);
                bf[nt][1] = __float_as_uint(Bs_s[(ks + tig + 4)*BSTR + c]);
            }
            #pragma unroll
            for (int mt = 0; mt < 4; ++mt)
                #pragma unroll
                for (int nt = 0; nt < 4; ++nt)
                    asm volatile(
                        "mma.sync.aligned.m16n8k8.row.col.f32.tf32.tf32.f32 "
                        "{%0,%1,%2,%3}, {%4,%5,%6,%7}, {%8,%9}, {%0,%1,%2,%3};"
                        : "+f"(acc[mt][nt][0]), "+f"(acc[mt][nt][1]),
                          "+f"(acc[mt][nt][2]), "+f"(acc[mt][nt][3])
                        : "r"(af[mt][0]), "r"(af[mt][1]), "r"(af[mt][2]), "r"(af[mt][3]),
                          "r"(bf[nt][0]), "r"(bf[nt][1]));
        }
    }

    // epilogue: bias + store
    float2 bv[4];
    #pragma unroll
    for (int nt = 0; nt < 4; ++nt){
        int c = warpN*32 + nt*8 + tig*2;
        bv[nt] = make_float2(__ldg(bias + c), __ldg(bias + c + 1));
    }
    #pragma unroll
    for (int mt = 0; mt < 4; ++mt){
        int r0 = row0 + warpM*64 + mt*16 + g;
        #pragma unroll
        for (int nt = 0; nt < 4; ++nt){
            int c = warpN*32 + nt*8 + tig*2;
            if (r0 < NROWS)
                *(float2*)(out + (size_t)r0*COUT + c) =
                    make_float2(acc[mt][nt][0] + bv[nt].x, acc[mt][nt][1] + bv[nt].y);
            if (r0 + 8 < NROWS)
                *(float2*)(out + (size_t)(r0+8)*COUT + c) =
                    make_float2(acc[mt][nt][2] + bv[nt].x, acc[mt][nt][3] + bv[nt].y);
        }
    }
}

extern "C" void kernel_launch(void* const* d_in, const int* in_sizes, int n_in,
                              void* d_out, int out_size){
    const float* x    = (const float*)d_in[0];   // (2,20000,128) f32
    const int*   adj  = (const int*)  d_in[1];   // (20000,16)    i32
    const float* W    = (const float*)d_in[2];   // (9,128,128)   f32
    const float* bias = (const float*)d_in[3];   // (128,)        f32
    const float* u    = (const float*)d_in[4];   // (9,128)       f32
    const float* cb   = (const float*)d_in[5];   // (9,)          f32
    float* out = (float*)d_out;                  // (2,20000,128) f32

    cudaFuncSetAttribute(fused_kernel,
                         cudaFuncAttributeMaxDynamicSharedMemorySize, GSMEM_BYTES);

    xu_kernel<<<NROWS/8, 256>>>(x, u);
    wt_kernel<<<(MM*COUT*CIN + 255)/256, 256>>>(W);
    fused_kernel<<<(NROWS + BMg - 1)/BMg, 256, GSMEM_BYTES>>>(x, adj, cb, bias, out);
}

// round 12
// speedup vs baseline: 1.9645x; 1.9645x over previous
#include <cuda_runtime.h>
#include <cuda_fp16.h>
#include <cstdint>

// Problem shape (fixed by the dataset)
#define BB   2
#define NN   20000
#define KK   16
#define CIN  128
#define MM   9
#define COUT 128
#define MP   16
#define NROWS (BB*NN)           // 40000
#define KDIM  (MM*CIN)          // 1152

// Scratch (device globals: allocation-free per harness rules)
__device__ float  g_xu[(size_t)NROWS * MP];       // 2.56 MB
__device__ __half g_Yh[(size_t)NROWS * KDIM];     // 92 MB  Y (fp16)
__device__ __half g_WH[(size_t)COUT * KDIM];      // 295 KB WH[o][m*128+c] (fp16)

// ---- packed f32x2 helpers (for qy inner product) -------------------------
__device__ __forceinline__ unsigned long long pk2(float lo, float hi){
    unsigned long long r;
    asm("mov.b64 %0, {%1, %2};" : "=l"(r) : "f"(lo), "f"(hi));
    return r;
}
__device__ __forceinline__ void fma2(unsigned long long& d,
                                     unsigned long long a, unsigned long long b){
    asm("fma.rn.f32x2 %0, %1, %2, %0;" : "+l"(d) : "l"(a), "l"(b));
}
__device__ __forceinline__ float2 up2(unsigned long long v){
    float lo, hi;
    asm("mov.b64 {%0, %1}, %2;" : "=f"(lo), "=f"(hi) : "l"(v));
    return make_float2(lo, hi);
}
__device__ __forceinline__ uint32_t smem_u32(const void* p){
    uint32_t a;
    asm("{ .reg .u64 t; cvta.to.shared.u64 t, %1; cvt.u32.u64 %0, t; }" : "=r"(a) : "l"(p));
    return a;
}
__device__ __forceinline__ void cpasync16(uint32_t dst, const void* src, bool pred){
    int sz = pred ? 16 : 0;
    asm volatile("cp.async.cg.shared.global [%0], [%1], 16, %2;"
                 :: "r"(dst), "l"(src), "r"(sz) : "memory");
}

// ---- Kernel A: xu[b,n,m] = dot(x[b,n,:], u[m,:]) -------------------------
__global__ void xu_kernel(const float* __restrict__ x, const float* __restrict__ u){
    __shared__ float su[MM*CIN];
    for (int i = threadIdx.x; i < MM*CIN; i += blockDim.x) su[i] = u[i];
    __syncthreads();
    int gw  = (blockIdx.x * blockDim.x + threadIdx.x) >> 5;
    int lid = threadIdx.x & 31;
    if (gw >= NROWS) return;
    float4 xv = *(const float4*)(x + (size_t)gw*CIN + lid*4);
    float p[MM];
    #pragma unroll
    for (int m = 0; m < MM; ++m){
        float4 uv = *(const float4*)(su + m*CIN + lid*4);
        p[m] = xv.x*uv.x + xv.y*uv.y + xv.z*uv.z + xv.w*uv.w;
    }
    #pragma unroll
    for (int off = 16; off; off >>= 1)
        #pragma unroll
        for (int m = 0; m < MM; ++m)
            p[m] += __shfl_xor_sync(0xffffffffu, p[m], off);
    if (lid == 0){
        float* dst = g_xu + (size_t)gw*MP;
        #pragma unroll
        for (int m = 0; m < MM; ++m) dst[m] = p[m];
    }
}

// ---- Kernel B: W[m][o][c] -> WH[o][m*128+c], fp16 ------------------------
__global__ void wt_kernel(const float* __restrict__ W){
    int idx = blockIdx.x*blockDim.x + threadIdx.x;     // dst index
    if (idx >= MM*COUT*CIN) return;
    int c = idx % CIN;
    int m = (idx / CIN) % MM;
    int o = idx / (CIN*MM);
    g_WH[(size_t)o*KDIM + m*CIN + c] =
        __float2half_rn(W[(size_t)m*COUT*CIN + o*CIN + c]);
}

// ---- Kernel C: softmax q (deg_inv folded) + Y materialize (fp16) ---------
#define QY_WARPS 8
__global__ void qy_kernel(const float* __restrict__ x, const int* __restrict__ adj,
                          const float* __restrict__ cb){
    __shared__ float qs[QY_WARPS][KK][MM];
    int lid  = threadIdx.x & 31;
    int w    = threadIdx.x >> 5;
    int node = blockIdx.x * QY_WARPS + w;
    if (node >= NROWS) return;
    int b = node / NN;
    int n = node - b*NN;

    int j = 0;
    if (lid < KK) j = adj[n*KK + lid];
    unsigned nz = __ballot_sync(0xffffffffu, j != 0);
    int   deg  = __popc(nz);
    float dinv = (deg > 0) ? (1.0f / (float)deg) : 0.0f;

    if (lid < KK){
        if (j != 0){
            const float* xs = g_xu + (size_t)node * MP;
            const float* xp = g_xu + (size_t)(b*NN + (j-1)) * MP;
            float lg[MM]; float mx = -1e30f;
            #pragma unroll
            for (int m = 0; m < MM; ++m){
                lg[m] = xs[m] - xp[m] + cb[m];
                mx = fmaxf(mx, lg[m]);
            }
            float s = 0.f;
            #pragma unroll
            for (int m = 0; m < MM; ++m){ lg[m] = __expf(lg[m] - mx); s += lg[m]; }
            float r = dinv / s;
            #pragma unroll
            for (int m = 0; m < MM; ++m) qs[w][lid][m] = lg[m] * r;
        } else {
            #pragma unroll
            for (int m = 0; m < MM; ++m) qs[w][lid][m] = 0.f;
        }
    }
    __syncwarp();

    unsigned long long acc[MM][2];
    #pragma unroll
    for (int m = 0; m < MM; ++m){ acc[m][0] = 0ull; acc[m][1] = 0ull; }

    #pragma unroll
    for (int k = 0; k < KK; ++k){
        int jk = __shfl_sync(0xffffffffu, j, k);
        if (jk == 0) continue;
        float4 p = *(const float4*)(x + (size_t)(b*NN + (jk-1))*CIN + lid*4);
        unsigned long long p0 = pk2(p.x, p.y), p1 = pk2(p.z, p.w);
        #pragma unroll
        for (int m = 0; m < MM; ++m){
            float qv = qs[w][k][m];
            unsigned long long q2 = pk2(qv, qv);
            fma2(acc[m][0], q2, p0);
            fma2(acc[m][1], q2, p1);
        }
    }
    #pragma unroll
    for (int m = 0; m < MM; ++m){
        float2 a  = up2(acc[m][0]);
        float2 c2 = up2(acc[m][1]);
        __half2 h0 = __floats2half2_rn(a.x,  a.y);
        __half2 h1 = __floats2half2_rn(c2.x, c2.y);
        *(uint2*)(g_Yh + (size_t)node*KDIM + m*CIN + lid*4) =
            make_uint2(*(uint32_t*)&h0, *(uint32_t*)&h1);
    }
}

// ---- Kernel D: fp16 m16n8k16 mma.sync GEMM  out = Y x W^T + bias ---------
// BM=128, BN=128(=COUT), BK=32 halves, 256 threads (8 warps, 64x32 warp
// tiles), 3-stage cp.async pipeline, tail-safe drain. B held o-major in
// smem so fragments are contiguous half2 loads. Stride 40 halves (20 half2
// units): banks (g*20+tig) mod 32 all distinct -> conflict-free.
#define BMg 128
#define BKH 32                    // halves per stage per row
#define ASTRH 40                  // halves stride (20 half2 units)
#define AST_B (BMg*ASTRH*2)       // 10240 bytes per A stage
#define BST_B (COUT*ASTRH*2)      // 10240 bytes per B stage
#define BOFF_B (3*AST_B)          // 30720
#define GSMEM_BYTES (3*AST_B + 3*BST_B)   // 61440
#define NTg (KDIM/BKH)            // 36

__global__ void __launch_bounds__(256, 2)
gemm_kernel(const float* __restrict__ bias, float* __restrict__ out){
    extern __shared__ char smch[];
    int tid  = threadIdx.x;
    int lane = tid & 31, wid = tid >> 5;
    int warpM = wid >> 2, warpN = wid & 3;       // 2 x 4 warp grid, tile 64x32
    int g = lane >> 2, tig = lane & 3;
    int row0 = blockIdx.x * BMg;

    uint32_t smb = smem_u32(smch);
    bool isA = tid < 128;
    bool arow_ok = isA && (row0 + tid) < NROWS;
    const __half* Abase = g_Yh + (size_t)(arow_ok ? (row0 + tid) : 0) * KDIM;
    const __half* Bbase = g_WH + (size_t)(isA ? 0 : (tid - 128)) * KDIM;

    float acc[4][4][4];
    #pragma unroll
    for (int mt = 0; mt < 4; ++mt)
        #pragma unroll
        for (int nt = 0; nt < 4; ++nt)
            #pragma unroll
            for (int i = 0; i < 4; ++i) acc[mt][nt][i] = 0.f;

    auto load_stage = [&](int t, int s){
        int kc = t * BKH;                      // in halves
        if (isA){
            uint32_t d = smb + s*AST_B + tid*(ASTRH*2);
            #pragma unroll
            for (int c = 0; c < 4; ++c)
                cpasync16(d + c*16, Abase + kc + c*8, arow_ok);
        } else {
            uint32_t d = smb + BOFF_B + s*BST_B + (tid-128)*(ASTRH*2);
            #pragma unroll
            for (int c = 0; c < 4; ++c)
                cpasync16(d + c*16, Bbase + kc + c*8, true);
        }
        asm volatile("cp.async.commit_group;" ::: "memory");
    };

    load_stage(0, 0);
    load_stage(1, 1);

    for (int t = 0; t < NTg; ++t){
        int s = t % 3;
        // Committed-not-drained groups here: {t} plus {t+1} if it exists.
        if (t + 1 < NTg)
            asm volatile("cp.async.wait_group 1;" ::: "memory");
        else
            asm volatile("cp.async.wait_group 0;" ::: "memory");
        __syncthreads();
        if (t + 2 < NTg) load_stage(t + 2, (t + 2) % 3);

        const uint32_t* As_s = (const uint32_t*)(smch + s*AST_B);           // half2 units, stride 20
        const uint32_t* Bs_s = (const uint32_t*)(smch + BOFF_B + s*BST_B);  // half2 units, stride 20
        #pragma unroll
        for (int ks = 0; ks < 2; ++ks){          // two k16 steps per stage
            uint32_t af[4][4], bf[4][2];
            #pragma unroll
            for (int mt = 0; mt < 4; ++mt){
                int r = warpM*64 + mt*16 + g;
                af[mt][0] = As_s[r*20     + ks*8 + tig    ];
                af[mt][1] = As_s[(r+8)*20 + ks*8 + tig    ];
                af[mt][2] = As_s[r*20     + ks*8 + tig + 4];
                af[mt][3] = As_s[(r+8)*20 + ks*8 + tig + 4];
            }
            #pragma unroll
            for (int nt = 0; nt < 4; ++nt){
                int c = warpN*32 + nt*8 + g;
                bf[nt][0] = Bs_s[c*20 + ks*8 + tig    ];
                bf[nt][1] = Bs_s[c*20 + ks*8 + tig + 4];
            }
            #pragma unroll
            for (int mt = 0; mt < 4; ++mt)
                #pragma unroll
                for (int nt = 0; nt < 4; ++nt)
                    asm volatile(
                        "mma.sync.aligned.m16n8k16.row.col.f32.f16.f16.f32 "
                        "{%0,%1,%2,%3}, {%4,%5,%6,%7}, {%8,%9}, {%0,%1,%2,%3};"
                        : "+f"(acc[mt][nt][0]), "+f"(acc[mt][nt][1]),
                          "+f"(acc[mt][nt][2]), "+f"(acc[mt][nt][3])
                        : "r"(af[mt][0]), "r"(af[mt][1]), "r"(af[mt][2]), "r"(af[mt][3]),
                          "r"(bf[nt][0]), "r"(bf[nt][1]));
        }
    }

    // epilogue: bias + store
    float2 bv[4];
    #pragma unroll
    for (int nt = 0; nt < 4; ++nt){
        int c = warpN*32 + nt*8 + tig*2;
        bv[nt] = make_float2(__ldg(bias + c), __ldg(bias + c + 1));
    }
    #pragma unroll
    for (int mt = 0; mt < 4; ++mt){
        int r0 = row0 + warpM*64 + mt*16 + g;
        #pragma unroll
        for (int nt = 0; nt < 4; ++nt){
            int c = warpN*32 + nt*8 + tig*2;
            if (r0 < NROWS)
                *(float2*)(out + (size_t)r0*COUT + c) =
                    make_float2(acc[mt][nt][0] + bv[nt].x, acc[mt][nt][1] + bv[nt].y);
            if (r0 + 8 < NROWS)
                *(float2*)(out + (size_t)(r0+8)*COUT + c) =
                    make_float2(acc[mt][nt][2] + bv[nt].x, acc[mt][nt][3] + bv[nt].y);
        }
    }
}

extern "C" void kernel_launch(void* const* d_in, const int* in_sizes, int n_in,
                              void* d_out, int out_size){
    const float* x    = (const float*)d_in[0];   // (2,20000,128) f32
    const int*   adj  = (const int*)  d_in[1];   // (20000,16)    i32
    const float* W    = (const float*)d_in[2];   // (9,128,128)   f32
    const float* bias = (const float*)d_in[3];   // (128,)        f32
    const float* u    = (const float*)d_in[4];   // (9,128)       f32
    const float* cb   = (const float*)d_in[5];   // (9,)          f32
    float* out = (float*)d_out;                  // (2,20000,128) f32

    cudaFuncSetAttribute(gemm_kernel,
                         cudaFuncAttributeMaxDynamicSharedMemorySize, GSMEM_BYTES);

    xu_kernel<<<NROWS/8, 256>>>(x, u);
    wt_kernel<<<(MM*COUT*CIN + 255)/256, 256>>>(W);
    qy_kernel<<<NROWS/QY_WARPS, 256>>>(x, adj, cb);
    gemm_kernel<<<(NROWS + BMg - 1)/BMg, 256, GSMEM_BYTES>>>(bias, out);
}

// round 13
// speedup vs baseline: 2.3525x; 1.1975x over previous
#include <cuda_runtime.h>
#include <cuda_fp16.h>
#include <cstdint>

// Problem shape (fixed by the dataset)
#define BB   2
#define NN   20000
#define KK   16
#define CIN  128
#define MM   9
#define COUT 128
#define MP   16
#define NROWS (BB*NN)           // 40000
#define KDIM  (MM*CIN)          // 1152

// Scratch (device globals: allocation-free per harness rules)
__device__ float  g_xu[(size_t)NROWS * MP];       // 2.56 MB
__device__ __half g_Yh[(size_t)NROWS * KDIM];     // 92 MB  Y (fp16)
__device__ __half g_WH[(size_t)COUT * KDIM];      // 295 KB WH[o][m*128+c] (fp16)

// ---- packed f32x2 helpers (for qy inner product) -------------------------
__device__ __forceinline__ unsigned long long pk2(float lo, float hi){
    unsigned long long r;
    asm("mov.b64 %0, {%1, %2};" : "=l"(r) : "f"(lo), "f"(hi));
    return r;
}
__device__ __forceinline__ void fma2(unsigned long long& d,
                                     unsigned long long a, unsigned long long b){
    asm("fma.rn.f32x2 %0, %1, %2, %0;" : "+l"(d) : "l"(a), "l"(b));
}
__device__ __forceinline__ float2 up2(unsigned long long v){
    float lo, hi;
    asm("mov.b64 {%0, %1}, %2;" : "=f"(lo), "=f"(hi) : "l"(v));
    return make_float2(lo, hi);
}
__device__ __forceinline__ uint32_t smem_u32(const void* p){
    uint32_t a;
    asm("{ .reg .u64 t; cvta.to.shared.u64 t, %1; cvt.u32.u64 %0, t; }" : "=r"(a) : "l"(p));
    return a;
}
__device__ __forceinline__ void cpasync16(uint32_t dst, const void* src, bool pred){
    int sz = pred ? 16 : 0;
    asm volatile("cp.async.cg.shared.global [%0], [%1], 16, %2;"
                 :: "r"(dst), "l"(src), "r"(sz) : "memory");
}

// ---- Kernel A: xu[b,n,m] = dot(x[b,n,:], u[m,:]) — u held in registers ---
__global__ void xu_kernel(const float* __restrict__ x, const float* __restrict__ u){
    int gw  = (blockIdx.x * blockDim.x + threadIdx.x) >> 5;
    int lid = threadIdx.x & 31;
    float4 uv[MM];
    #pragma unroll
    for (int m = 0; m < MM; ++m)
        uv[m] = *(const float4*)(u + m*CIN + lid*4);   // L1-broadcast, loaded once
    if (gw >= NROWS) return;
    float4 xv = *(const float4*)(x + (size_t)gw*CIN + lid*4);
    float p[MM];
    #pragma unroll
    for (int m = 0; m < MM; ++m)
        p[m] = xv.x*uv[m].x + xv.y*uv[m].y + xv.z*uv[m].z + xv.w*uv[m].w;
    #pragma unroll
    for (int off = 16; off; off >>= 1)
        #pragma unroll
        for (int m = 0; m < MM; ++m)
            p[m] += __shfl_xor_sync(0xffffffffu, p[m], off);
    if (lid == 0){
        float* dst = g_xu + (size_t)gw*MP;
        #pragma unroll
        for (int m = 0; m < MM; ++m) dst[m] = p[m];
    }
}

// ---- Kernel B: W[m][o][c] -> WH[o][m*128+c], fp16 ------------------------
__global__ void wt_kernel(const float* __restrict__ W){
    int idx = blockIdx.x*blockDim.x + threadIdx.x;     // dst index
    if (idx >= MM*COUT*CIN) return;
    int c = idx % CIN;
    int m = (idx / CIN) % MM;
    int o = idx / (CIN*MM);
    g_WH[(size_t)o*KDIM + m*CIN + c] =
        __float2half_rn(W[(size_t)m*COUT*CIN + o*CIN + c]);
}

// ---- Kernel C: softmax q (deg_inv folded) + Y materialize (fp16) ---------
// Branchless gather: q rows for j==0 are exact zeros, so we load a dummy
// valid row and accumulate 0*patch (bit-exact). Patches prefetched in two
// batches of 8 LDG.128 (MLP=8) to hide L2/DRAM latency.
#define QY_WARPS 8
__global__ void qy_kernel(const float* __restrict__ x, const int* __restrict__ adj,
                          const float* __restrict__ cb){
    __shared__ float qs[QY_WARPS][KK][MM];
    int lid  = threadIdx.x & 31;
    int w    = threadIdx.x >> 5;
    int node = blockIdx.x * QY_WARPS + w;        // grid is exact: 5000*8=40000
    int b = node / NN;
    int n = node - b*NN;

    int j = 0;
    if (lid < KK) j = adj[n*KK + lid];
    unsigned nz = __ballot_sync(0xffffffffu, j != 0);
    int   deg  = __popc(nz);
    float dinv = (deg > 0) ? (1.0f / (float)deg) : 0.0f;

    if (lid < KK){
        if (j != 0){
            const float* xs = g_xu + (size_t)node * MP;
            const float* xp = g_xu + (size_t)(b*NN + (j-1)) * MP;
            float lg[MM]; float mx = -1e30f;
            #pragma unroll
            for (int m = 0; m < MM; ++m){
                lg[m] = xs[m] - xp[m] + cb[m];
                mx = fmaxf(mx, lg[m]);
            }
            float s = 0.f;
            #pragma unroll
            for (int m = 0; m < MM; ++m){ lg[m] = __expf(lg[m] - mx); s += lg[m]; }
            float r = dinv / s;
            #pragma unroll
            for (int m = 0; m < MM; ++m) qs[w][lid][m] = lg[m] * r;
        } else {
            #pragma unroll
            for (int m = 0; m < MM; ++m) qs[w][lid][m] = 0.f;
        }
    }
    __syncwarp();

    // All 16 gather rows (dummy row b*NN for j==0; its q is 0)
    int rows[KK];
    #pragma unroll
    for (int k = 0; k < KK; ++k){
        int jk = __shfl_sync(0xffffffffu, j, k);
        rows[k] = b*NN + (jk > 0 ? jk - 1 : 0);
    }

    unsigned long long acc[MM][2];
    #pragma unroll
    for (int m = 0; m < MM; ++m){ acc[m][0] = 0ull; acc[m][1] = 0ull; }

    #pragma unroll
    for (int half = 0; half < 2; ++half){
        float4 p[8];
        #pragma unroll
        for (int kk = 0; kk < 8; ++kk)
            p[kk] = *(const float4*)(x + (size_t)rows[half*8 + kk]*CIN + lid*4);
        #pragma unroll
        for (int kk = 0; kk < 8; ++kk){
            unsigned long long p0 = pk2(p[kk].x, p[kk].y), p1 = pk2(p[kk].z, p[kk].w);
            const float* qk = &qs[w][half*8 + kk][0];
            #pragma unroll
            for (int m = 0; m < MM; ++m){
                float qv = qk[m];
                unsigned long long q2 = pk2(qv, qv);
                fma2(acc[m][0], q2, p0);
                fma2(acc[m][1], q2, p1);
            }
        }
    }
    #pragma unroll
    for (int m = 0; m < MM; ++m){
        float2 a  = up2(acc[m][0]);
        float2 c2 = up2(acc[m][1]);
        __half2 h0 = __floats2half2_rn(a.x,  a.y);
        __half2 h1 = __floats2half2_rn(c2.x, c2.y);
        *(uint2*)(g_Yh + (size_t)node*KDIM + m*CIN + lid*4) =
            make_uint2(*(uint32_t*)&h0, *(uint32_t*)&h1);
    }
}

// ---- Kernel D: fp16 m16n8k16 mma.sync GEMM  out = Y x W^T + bias ---------
// BM=128, BN=128(=COUT), BK=32 halves, 256 threads (8 warps, 64x32 warp
// tiles), 3-stage cp.async pipeline, tail-safe drain. B held o-major in
// smem so fragments are contiguous half2 loads. Stride 40 halves (20 half2
// units): banks (g*20+tig) mod 32 all distinct -> conflict-free.
#define BMg 128
#define BKH 32                    // halves per stage per row
#define ASTRH 40                  // halves stride (20 half2 units)
#define AST_B (BMg*ASTRH*2)       // 10240 bytes per A stage
#define BST_B (COUT*ASTRH*2)      // 10240 bytes per B stage
#define BOFF_B (3*AST_B)          // 30720
#define GSMEM_BYTES (3*AST_B + 3*BST_B)   // 61440
#define NTg (KDIM/BKH)            // 36

__global__ void __launch_bounds__(256, 2)
gemm_kernel(const float* __restrict__ bias, float* __restrict__ out){
    extern __shared__ char smch[];
    int tid  = threadIdx.x;
    int lane = tid & 31, wid = tid >> 5;
    int warpM = wid >> 2, warpN = wid & 3;       // 2 x 4 warp grid, tile 64x32
    int g = lane >> 2, tig = lane & 3;
    int row0 = blockIdx.x * BMg;

    uint32_t smb = smem_u32(smch);
    bool isA = tid < 128;
    bool arow_ok = isA && (row0 + tid) < NROWS;
    const __half* Abase = g_Yh + (size_t)(arow_ok ? (row0 + tid) : 0) * KDIM;
    const __half* Bbase = g_WH + (size_t)(isA ? 0 : (tid - 128)) * KDIM;

    float acc[4][4][4];
    #pragma unroll
    for (int mt = 0; mt < 4; ++mt)
        #pragma unroll
        for (int nt = 0; nt < 4; ++nt)
            #pragma unroll
            for (int i = 0; i < 4; ++i) acc[mt][nt][i] = 0.f;

    auto load_stage = [&](int t, int s){
        int kc = t * BKH;                      // in halves
        if (isA){
            uint32_t d = smb + s*AST_B + tid*(ASTRH*2);
            #pragma unroll
            for (int c = 0; c < 4; ++c)
                cpasync16(d + c*16, Abase + kc + c*8, arow_ok);
        } else {
            uint32_t d = smb + BOFF_B + s*BST_B + (tid-128)*(ASTRH*2);
            #pragma unroll
            for (int c = 0; c < 4; ++c)
                cpasync16(d + c*16, Bbase + kc + c*8, true);
        }
        asm volatile("cp.async.commit_group;" ::: "memory");
    };

    load_stage(0, 0);
    load_stage(1, 1);

    for (int t = 0; t < NTg; ++t){
        int s = t % 3;
        // Committed-not-drained groups here: {t} plus {t+1} if it exists.
        if (t + 1 < NTg)
            asm volatile("cp.async.wait_group 1;" ::: "memory");
        else
            asm volatile("cp.async.wait_group 0;" ::: "memory");
        __syncthreads();
        if (t + 2 < NTg) load_stage(t + 2, (t + 2) % 3);

        const uint32_t* As_s = (const uint32_t*)(smch + s*AST_B);           // half2 units, stride 20
        const uint32_t* Bs_s = (const uint32_t*)(smch + BOFF_B + s*BST_B);  // half2 units, stride 20
        #pragma unroll
        for (int ks = 0; ks < 2; ++ks){          // two k16 steps per stage
            uint32_t af[4][4], bf[4][2];
            #pragma unroll
            for (int mt = 0; mt < 4; ++mt){
                int r = warpM*64 + mt*16 + g;
                af[mt][0] = As_s[r*20     + ks*8 + tig    ];
                af[mt][1] = As_s[(r+8)*20 + ks*8 + tig    ];
                af[mt][2] = As_s[r*20     + ks*8 + tig + 4];
                af[mt][3] = As_s[(r+8)*20 + ks*8 + tig + 4];
            }
            #pragma unroll
            for (int nt = 0; nt < 4; ++nt){
                int c = warpN*32 + nt*8 + g;
                bf[nt][0] = Bs_s[c*20 + ks*8 + tig    ];
                bf[nt][1] = Bs_s[c*20 + ks*8 + tig + 4];
            }
            #pragma unroll
            for (int mt = 0; mt < 4; ++mt)
                #pragma unroll
                for (int nt = 0; nt < 4; ++nt)
                    asm volatile(
                        "mma.sync.aligned.m16n8k16.row.col.f32.f16.f16.f32 "
                        "{%0,%1,%2,%3}, {%4,%5,%6,%7}, {%8,%9}, {%0,%1,%2,%3};"
                        : "+f"(acc[mt][nt][0]), "+f"(acc[mt][nt][1]),
                          "+f"(acc[mt][nt][2]), "+f"(acc[mt][nt][3])
                        : "r"(af[mt][0]), "r"(af[mt][1]), "r"(af[mt][2]), "r"(af[mt][3]),
                          "r"(bf[nt][0]), "r"(bf[nt][1]));
        }
    }

    // epilogue: bias + store
    float2 bv[4];
    #pragma unroll
    for (int nt = 0; nt < 4; ++nt){
        int c = warpN*32 + nt*8 + tig*2;
        bv[nt] = make_float2(__ldg(bias + c), __ldg(bias + c + 1));
    }
    #pragma unroll
    for (int mt = 0; mt < 4; ++mt){
        int r0 = row0 + warpM*64 + mt*16 + g;
        #pragma unroll
        for (int nt = 0; nt < 4; ++nt){
            int c = warpN*32 + nt*8 + tig*2;
            if (r0 < NROWS)
                *(float2*)(out + (size_t)r0*COUT + c) =
                    make_float2(acc[mt][nt][0] + bv[nt].x, acc[mt][nt][1] + bv[nt].y);
            if (r0 + 8 < NROWS)
                *(float2*)(out + (size_t)(r0+8)*COUT + c) =
                    make_float2(acc[mt][nt][2] + bv[nt].x, acc[mt][nt][3] + bv[nt].y);
        }
    }
}

extern "C" void kernel_launch(void* const* d_in, const int* in_sizes, int n_in,
                              void* d_out, int out_size){
    const float* x    = (const float*)d_in[0];   // (2,20000,128) f32
    const int*   adj  = (const int*)  d_in[1];   // (20000,16)    i32
    const float* W    = (const float*)d_in[2];   // (9,128,128)   f32
    const float* bias = (const float*)d_in[3];   // (128,)        f32
    const float* u    = (const float*)d_in[4];   // (9,128)       f32
    const float* cb   = (const float*)d_in[5];   // (9,)          f32
    float* out = (float*)d_out;                  // (2,20000,128) f32

    cudaFuncSetAttribute(gemm_kernel,
                         cudaFuncAttributeMaxDynamicSharedMemorySize, GSMEM_BYTES);

    xu_kernel<<<NROWS/8, 256>>>(x, u);
    wt_kernel<<<(MM*COUT*CIN + 255)/256, 256>>>(W);
    qy_kernel<<<NROWS/QY_WARPS, 256>>>(x, adj, cb);
    gemm_kernel<<<(NROWS + BMg - 1)/BMg, 256, GSMEM_BYTES>>>(bias, out);
}